// round 1
// baseline (speedup 1.0000x reference)
#include <cuda_runtime.h>
#include <math.h>

// ---------------------------------------------------------------------------
// Binarized network, fully fused.
//
// Stage 0 (prep kernel, tiny): binarize all weights into 32-bit channel words,
// and convert every bintanh(bn(conv+bias)) into an integer popcount threshold
// by scanning all reachable integer pre-activations through the reference's
// exact float formula. Also builds a 65-entry sigmoid LUT for the final fc3.
//
// Stage 1 (main kernel): one thread per batch element.
//   s0  = conv0+bn+sign  -> 16 words (bit c of word l = sign of channel c at pos l)
//   4 residual blocks: y = s_i + s0 (two binary planes); conv = XNOR+POPC.
//   fc1/fc2 likewise popcount dots vs integer thresholds; fc3 via sigmoid LUT.
// ---------------------------------------------------------------------------

struct Params {
    float    c0[32][8];      // per out-ch: s0,s1,s2,s3, conv_b, bn_m, bn_scale, bn_b
    unsigned Wb[4][32][3];   // conv block weight bits (bit c)
    int      PmI[4][32];     // interior popcount threshold (P <= PmI -> +1)
    int      PmE[4][32];     // edge popcount threshold
    unsigned W1[64][16];     // fc1 weight bits, word l, bit c  (f idx = c*16+l)
    int      P5[64];
    unsigned W2[64][2];
    int      P6[64];
    unsigned W3[2];
    float    sig[65];        // sigmoid(64-2p + fc3_b)
};

__device__ Params g_p;

__device__ __forceinline__ float bnval(float z, float cb, float m, float sc, float bb) {
    float t1 = z + cb;       // + bias
    float t2 = t1 - m;       // - running mean
    return fmaf(t2, sc, bb); // * scale + beta
}

__global__ void prep_kernel(
    const float* conv0_w, const float* conv0_b,
    const float* bn0_g, const float* bn0_b, const float* bn0_m, const float* bn0_v,
    const float* convs_w, const float* convs_b,
    const float* bns_g, const float* bns_b, const float* bns_m, const float* bns_v,
    const float* fc1_w, const float* fc1_b,
    const float* bn5_g, const float* bn5_b, const float* bn5_m, const float* bn5_v,
    const float* fc2_w, const float* fc2_b,
    const float* bn6_g, const float* bn6_b, const float* bn6_m, const float* bn6_v,
    const float* fc3_w, const float* fc3_b)
{
    const int t = threadIdx.x;
    const int nt = blockDim.x;

    // conv0 params (sign floats + bn constants)
    for (int o = t; o < 32; o += nt) {
        for (int c = 0; c < 4; c++)
            g_p.c0[o][c] = (conv0_w[o * 4 + c] >= 0.f) ? 1.f : -1.f;
        float sc = __fdiv_rn(bn0_g[o], __fsqrt_rn(bn0_v[o] + 0.01f));
        g_p.c0[o][4] = conv0_b[o];
        g_p.c0[o][5] = bn0_m[o];
        g_p.c0[o][6] = sc;
        g_p.c0[o][7] = bn0_b[o];
    }

    // conv block weight bits: convs_w[i][o][c][k], bit c of Wb[i][o][k]
    for (int idx = t; idx < 4 * 32 * 3; idx += nt) {
        int k = idx % 3, o = (idx / 3) % 32, i = idx / 96;
        unsigned w = 0;
        for (int c = 0; c < 32; c++)
            if (convs_w[((i * 32 + o) * 32 + c) * 3 + k] >= 0.f) w |= 1u << c;
        g_p.Wb[i][o][k] = w;
    }

    // conv block integer thresholds (z is always even; bn is monotone in z)
    for (int idx = t; idx < 128; idx += nt) {
        int i = idx / 32, o = idx % 32;
        int oi = i * 32 + o;
        float cb = convs_b[oi], m = bns_m[oi], bb = bns_b[oi];
        float sc = __fdiv_rn(bns_g[oi], __fsqrt_rn(bns_v[oi] + 0.01f));
        int Ci = (i == 0) ? 96 : 192;   // planes * 32 * 3
        int Ce = (i == 0) ? 64 : 128;   // planes * 32 * 2 (edge positions)
        int zth = Ci + 4;
        for (int z = -(Ci + 2); z <= Ci + 2; z += 2)
            if (bnval((float)z, cb, m, sc, bb) >= 0.f) { zth = z; break; }
        g_p.PmI[i][o] = (Ci - zth) / 2;
        g_p.PmE[i][o] = (Ce - zth) / 2;
    }

    // fc1 weight bits: f index = c*16 + l -> word l, bit c
    for (int idx = t; idx < 64 * 16; idx += nt) {
        int l = idx % 16, o = idx / 16;
        unsigned w = 0;
        for (int c = 0; c < 32; c++)
            if (fc1_w[o * 512 + c * 16 + l] >= 0.f) w |= 1u << c;
        g_p.W1[o][l] = w;
    }
    for (int o = t; o < 64; o += nt) {
        float cb = fc1_b[o], m = bn5_m[o], bb = bn5_b[o];
        float sc = __fdiv_rn(bn5_g[o], __fsqrt_rn(bn5_v[o] + 0.01f));
        int zth = 1028;
        for (int z = -1026; z <= 1026; z += 2)
            if (bnval((float)z, cb, m, sc, bb) >= 0.f) { zth = z; break; }
        g_p.P5[o] = (1024 - zth) / 2;
    }

    // fc2
    for (int idx = t; idx < 128; idx += nt) {
        int j = idx % 2, o = idx / 2;
        unsigned w = 0;
        for (int c = 0; c < 32; c++)
            if (fc2_w[o * 64 + j * 32 + c] >= 0.f) w |= 1u << c;
        g_p.W2[o][j] = w;
    }
    for (int o = t; o < 64; o += nt) {
        float cb = fc2_b[o], m = bn6_m[o], bb = bn6_b[o];
        float sc = __fdiv_rn(bn6_g[o], __fsqrt_rn(bn6_v[o] + 0.01f));
        int zth = 68;
        for (int z = -66; z <= 66; z += 2)
            if (bnval((float)z, cb, m, sc, bb) >= 0.f) { zth = z; break; }
        g_p.P6[o] = (64 - zth) / 2;
    }

    // fc3
    if (t < 2) {
        unsigned w = 0;
        for (int c = 0; c < 32; c++)
            if (fc3_w[t * 32 + c] >= 0.f) w |= 1u << c;
        g_p.W3[t] = w;
    }
    for (int p = t; p < 65; p += nt) {
        float d = (float)(64 - 2 * p) + fc3_b[0];
        g_p.sig[p] = 1.f / (1.f + expf(-d));
    }
}

__global__ __launch_bounds__(256) void bnn_kernel(
    const float* __restrict__ x, float* __restrict__ out, int B)
{
    __shared__ Params sp;
    {
        const int n = (int)(sizeof(Params) / 4);
        const int* src = (const int*)&g_p;
        int* dst = (int*)&sp;
        for (int i = threadIdx.x; i < n; i += blockDim.x) dst[i] = src[i];
    }
    __syncthreads();

    int b = blockIdx.x * blockDim.x + threadIdx.x;
    if (b >= B) return;

    // ---- load x[b] : 4 channels x 16 positions --------------------------
    float xv[4][16];
    const float4* xp = (const float4*)(x + (size_t)b * 64);
#pragma unroll
    for (int c = 0; c < 4; c++)
#pragma unroll
        for (int q = 0; q < 4; q++) {
            float4 v = xp[c * 4 + q];
            xv[c][q * 4 + 0] = v.x; xv[c][q * 4 + 1] = v.y;
            xv[c][q * 4 + 2] = v.z; xv[c][q * 4 + 3] = v.w;
        }

    // ---- conv0 + bn0 + sign -> s0 bitplanes u0[16] ----------------------
    unsigned u0[16];
#pragma unroll
    for (int l = 0; l < 16; l++) u0[l] = 0;

    {
        unsigned mask = 1u;
#pragma unroll 2
        for (int o = 0; o < 32; o++) {
            float4 pA = *(const float4*)&sp.c0[o][0];
            float4 pB = *(const float4*)&sp.c0[o][4];
#pragma unroll
            for (int l = 0; l < 16; l++) {
                float y = pA.x * xv[0][l];                 // exact (+-x)
                y = fmaf(pA.y, xv[1][l], y);               // == sequential adds
                y = fmaf(pA.z, xv[2][l], y);
                y = fmaf(pA.w, xv[3][l], y);
                float t1 = y + pB.x;
                float t2 = t1 - pB.y;
                float v = fmaf(t2, pB.z, pB.w);
                if (v >= 0.f) u0[l] |= mask;
            }
            mask <<= 1;
        }
    }

    // ---- block 0: input = s0 (single plane) -----------------------------
    unsigned uc[16], un[16];
#pragma unroll
    for (int l = 0; l < 16; l++) un[l] = 0;
    {
        unsigned mask = 1u;
#pragma unroll 2
        for (int o = 0; o < 32; o++) {
            unsigned w0 = sp.Wb[0][o][0], w1 = sp.Wb[0][o][1], w2 = sp.Wb[0][o][2];
            int pmi = sp.PmI[0][o], pme = sp.PmE[0][o];
            {
                int P = __popc(u0[0] ^ w1) + __popc(u0[1] ^ w2);
                if (P <= pme) un[0] |= mask;
            }
#pragma unroll
            for (int l = 1; l < 15; l++) {
                int P = __popc(u0[l - 1] ^ w0) + __popc(u0[l] ^ w1) + __popc(u0[l + 1] ^ w2);
                if (P <= pmi) un[l] |= mask;
            }
            {
                int P = __popc(u0[14] ^ w0) + __popc(u0[15] ^ w1);
                if (P <= pme) un[15] |= mask;
            }
            mask <<= 1;
        }
    }
#pragma unroll
    for (int l = 0; l < 16; l++) uc[l] = un[l];

    // ---- blocks 1..3: input = s_i + s0 (two planes) ----------------------
#pragma unroll 1
    for (int i = 1; i < 4; i++) {
#pragma unroll
        for (int l = 0; l < 16; l++) un[l] = 0;
        unsigned mask = 1u;
#pragma unroll 2
        for (int o = 0; o < 32; o++) {
            unsigned w0 = sp.Wb[i][o][0], w1 = sp.Wb[i][o][1], w2 = sp.Wb[i][o][2];
            int pmi = sp.PmI[i][o], pme = sp.PmE[i][o];
            {
                int P = __popc(u0[0] ^ w1) + __popc(u0[1] ^ w2)
                      + __popc(uc[0] ^ w1) + __popc(uc[1] ^ w2);
                if (P <= pme) un[0] |= mask;
            }
#pragma unroll
            for (int l = 1; l < 15; l++) {
                int P = __popc(u0[l - 1] ^ w0) + __popc(u0[l] ^ w1) + __popc(u0[l + 1] ^ w2)
                      + __popc(uc[l - 1] ^ w0) + __popc(uc[l] ^ w1) + __popc(uc[l + 1] ^ w2);
                if (P <= pmi) un[l] |= mask;
            }
            {
                int P = __popc(u0[14] ^ w0) + __popc(u0[15] ^ w1)
                      + __popc(uc[14] ^ w0) + __popc(uc[15] ^ w1);
                if (P <= pme) un[15] |= mask;
            }
            mask <<= 1;
        }
#pragma unroll
        for (int l = 0; l < 16; l++) uc[l] = un[l];
    }

    // ---- fc1: f = s4 + s0 (two 512-bit planes) ---------------------------
    unsigned hb0 = 0, hb1 = 0;
    {
        unsigned mask = 1u;
#pragma unroll 2
        for (int o = 0; o < 32; o++) {
            int P = 0;
#pragma unroll
            for (int l = 0; l < 16; l++) {
                unsigned w = sp.W1[o][l];
                P += __popc(uc[l] ^ w) + __popc(u0[l] ^ w);
            }
            if (P <= sp.P5[o]) hb0 |= mask;
            mask <<= 1;
        }
        mask = 1u;
#pragma unroll 2
        for (int o = 32; o < 64; o++) {
            int P = 0;
#pragma unroll
            for (int l = 0; l < 16; l++) {
                unsigned w = sp.W1[o][l];
                P += __popc(uc[l] ^ w) + __popc(u0[l] ^ w);
            }
            if (P <= sp.P5[o]) hb1 |= mask;
            mask <<= 1;
        }
    }

    // ---- fc2 -------------------------------------------------------------
    unsigned gb0 = 0, gb1 = 0;
    {
        unsigned mask = 1u;
#pragma unroll 4
        for (int o = 0; o < 32; o++) {
            int P = __popc(hb0 ^ sp.W2[o][0]) + __popc(hb1 ^ sp.W2[o][1]);
            if (P <= sp.P6[o]) gb0 |= mask;
            mask <<= 1;
        }
        mask = 1u;
#pragma unroll 4
        for (int o = 32; o < 64; o++) {
            int P = __popc(hb0 ^ sp.W2[o][0]) + __popc(hb1 ^ sp.W2[o][1]);
            if (P <= sp.P6[o]) gb1 |= mask;
            mask <<= 1;
        }
    }

    // ---- fc3 + sigmoid (LUT) ----------------------------------------------
    int p3 = __popc(gb0 ^ sp.W3[0]) + __popc(gb1 ^ sp.W3[1]);
    out[b] = sp.sig[p3];
}

extern "C" void kernel_launch(void* const* d_in, const int* in_sizes, int n_in,
                              void* d_out, int out_size)
{
    const float* x       = (const float*)d_in[0];
    const float* conv0_w = (const float*)d_in[1];
    const float* conv0_b = (const float*)d_in[2];
    const float* bn0_g   = (const float*)d_in[3];
    const float* bn0_b   = (const float*)d_in[4];
    const float* bn0_m   = (const float*)d_in[5];
    const float* bn0_v   = (const float*)d_in[6];
    const float* convs_w = (const float*)d_in[7];
    const float* convs_b = (const float*)d_in[8];
    const float* bns_g   = (const float*)d_in[9];
    const float* bns_b   = (const float*)d_in[10];
    const float* bns_m   = (const float*)d_in[11];
    const float* bns_v   = (const float*)d_in[12];
    const float* fc1_w   = (const float*)d_in[13];
    const float* fc1_b   = (const float*)d_in[14];
    const float* bn5_g   = (const float*)d_in[15];
    const float* bn5_b   = (const float*)d_in[16];
    const float* bn5_m   = (const float*)d_in[17];
    const float* bn5_v   = (const float*)d_in[18];
    const float* fc2_w   = (const float*)d_in[19];
    const float* fc2_b   = (const float*)d_in[20];
    const float* bn6_g   = (const float*)d_in[21];
    const float* bn6_b   = (const float*)d_in[22];
    const float* bn6_m   = (const float*)d_in[23];
    const float* bn6_v   = (const float*)d_in[24];
    const float* fc3_w   = (const float*)d_in[25];
    const float* fc3_b   = (const float*)d_in[26];

    int B = in_sizes[0] / 64;   // (B, 4, 16)
    float* out = (float*)d_out;

    prep_kernel<<<1, 256>>>(conv0_w, conv0_b, bn0_g, bn0_b, bn0_m, bn0_v,
                            convs_w, convs_b, bns_g, bns_b, bns_m, bns_v,
                            fc1_w, fc1_b, bn5_g, bn5_b, bn5_m, bn5_v,
                            fc2_w, fc2_b, bn6_g, bn6_b, bn6_m, bn6_v,
                            fc3_w, fc3_b);

    int threads = 256;
    int blocks = (B + threads - 1) / threads;
    bnn_kernel<<<blocks, threads>>>(x, out, B);
}

// round 2
// speedup vs baseline: 1.4982x; 1.4982x over previous
#include <cuda_runtime.h>
#include <math.h>

// ---------------------------------------------------------------------------
// Binarized network, fully fused. v2:
//  - carry-save popcount for all two-plane dots:
//      popc(a^w)+popc(b^w) = popc(a^b) + 2*popc((a^w)&(b^w))
//    with (a^w)&(b^w) a single LOP3 and popc(a^b) precomputed per block.
//  - conv0 restructured in 4-position chunks (register pressure ~128 -> ~100)
//  - 64-thread CTAs for SM load balance (grid = B/64 = 1024)
// ---------------------------------------------------------------------------

struct Params {
    float    c0[32][8];      // per out-ch: s0,s1,s2,s3, conv_b, bn_m, bn_scale, bn_b
    unsigned Wb[4][32][3];   // conv block weight bits (bit c)
    int      PmI[4][32];     // interior popcount threshold (P <= PmI -> +1)
    int      PmE[4][32];     // edge popcount threshold
    unsigned W1[64][16];     // fc1 weight bits, word l, bit c  (f idx = c*16+l)
    int      P5[64];
    unsigned W2[64][2];
    int      P6[64];
    unsigned W3[2];
    float    sig[65];        // sigmoid(64-2p + fc3_b)
};

__device__ Params g_p;

__device__ __forceinline__ float bnval(float z, float cb, float m, float sc, float bb) {
    float t1 = z + cb;       // + bias
    float t2 = t1 - m;       // - running mean
    return fmaf(t2, sc, bb); // * scale + beta
}

__global__ void prep_kernel(
    const float* conv0_w, const float* conv0_b,
    const float* bn0_g, const float* bn0_b, const float* bn0_m, const float* bn0_v,
    const float* convs_w, const float* convs_b,
    const float* bns_g, const float* bns_b, const float* bns_m, const float* bns_v,
    const float* fc1_w, const float* fc1_b,
    const float* bn5_g, const float* bn5_b, const float* bn5_m, const float* bn5_v,
    const float* fc2_w, const float* fc2_b,
    const float* bn6_g, const float* bn6_b, const float* bn6_m, const float* bn6_v,
    const float* fc3_w, const float* fc3_b)
{
    const int t = threadIdx.x;
    const int nt = blockDim.x;

    for (int o = t; o < 32; o += nt) {
        for (int c = 0; c < 4; c++)
            g_p.c0[o][c] = (conv0_w[o * 4 + c] >= 0.f) ? 1.f : -1.f;
        float sc = __fdiv_rn(bn0_g[o], __fsqrt_rn(bn0_v[o] + 0.01f));
        g_p.c0[o][4] = conv0_b[o];
        g_p.c0[o][5] = bn0_m[o];
        g_p.c0[o][6] = sc;
        g_p.c0[o][7] = bn0_b[o];
    }

    for (int idx = t; idx < 4 * 32 * 3; idx += nt) {
        int k = idx % 3, o = (idx / 3) % 32, i = idx / 96;
        unsigned w = 0;
        for (int c = 0; c < 32; c++)
            if (convs_w[((i * 32 + o) * 32 + c) * 3 + k] >= 0.f) w |= 1u << c;
        g_p.Wb[i][o][k] = w;
    }

    for (int idx = t; idx < 128; idx += nt) {
        int i = idx / 32, o = idx % 32;
        int oi = i * 32 + o;
        float cb = convs_b[oi], m = bns_m[oi], bb = bns_b[oi];
        float sc = __fdiv_rn(bns_g[oi], __fsqrt_rn(bns_v[oi] + 0.01f));
        int Ci = (i == 0) ? 96 : 192;
        int Ce = (i == 0) ? 64 : 128;
        int zth = Ci + 4;
        for (int z = -(Ci + 2); z <= Ci + 2; z += 2)
            if (bnval((float)z, cb, m, sc, bb) >= 0.f) { zth = z; break; }
        g_p.PmI[i][o] = (Ci - zth) / 2;
        g_p.PmE[i][o] = (Ce - zth) / 2;
    }

    for (int idx = t; idx < 64 * 16; idx += nt) {
        int l = idx % 16, o = idx / 16;
        unsigned w = 0;
        for (int c = 0; c < 32; c++)
            if (fc1_w[o * 512 + c * 16 + l] >= 0.f) w |= 1u << c;
        g_p.W1[o][l] = w;
    }
    for (int o = t; o < 64; o += nt) {
        float cb = fc1_b[o], m = bn5_m[o], bb = bn5_b[o];
        float sc = __fdiv_rn(bn5_g[o], __fsqrt_rn(bn5_v[o] + 0.01f));
        int zth = 1028;
        for (int z = -1026; z <= 1026; z += 2)
            if (bnval((float)z, cb, m, sc, bb) >= 0.f) { zth = z; break; }
        g_p.P5[o] = (1024 - zth) / 2;
    }

    for (int idx = t; idx < 128; idx += nt) {
        int j = idx % 2, o = idx / 2;
        unsigned w = 0;
        for (int c = 0; c < 32; c++)
            if (fc2_w[o * 64 + j * 32 + c] >= 0.f) w |= 1u << c;
        g_p.W2[o][j] = w;
    }
    for (int o = t; o < 64; o += nt) {
        float cb = fc2_b[o], m = bn6_m[o], bb = bn6_b[o];
        float sc = __fdiv_rn(bn6_g[o], __fsqrt_rn(bn6_v[o] + 0.01f));
        int zth = 68;
        for (int z = -66; z <= 66; z += 2)
            if (bnval((float)z, cb, m, sc, bb) >= 0.f) { zth = z; break; }
        g_p.P6[o] = (64 - zth) / 2;
    }

    if (t < 2) {
        unsigned w = 0;
        for (int c = 0; c < 32; c++)
            if (fc3_w[t * 32 + c] >= 0.f) w |= 1u << c;
        g_p.W3[t] = w;
    }
    for (int p = t; p < 65; p += nt) {
        float d = (float)(64 - 2 * p) + fc3_b[0];
        g_p.sig[p] = 1.f / (1.f + expf(-p == p ? -d : -d));
    }
}

#define NT 64

__global__ __launch_bounds__(NT) void bnn_kernel(
    const float* __restrict__ x, float* __restrict__ out, int B)
{
    __shared__ Params sp;
    {
        const int n = (int)(sizeof(Params) / 4);
        const int* src = (const int*)&g_p;
        int* dst = (int*)&sp;
        for (int i = threadIdx.x; i < n; i += NT) dst[i] = src[i];
    }
    __syncthreads();

    int b = blockIdx.x * NT + threadIdx.x;
    if (b >= B) return;

    // ---- conv0 + bn0 + sign -> s0 bitplanes u0[16], 4 positions at a time --
    unsigned u0[16];
    const float4* xp = (const float4*)(x + (size_t)b * 64);
#pragma unroll
    for (int q = 0; q < 4; q++) {
        float4 x0 = xp[0 * 4 + q];
        float4 x1 = xp[1 * 4 + q];
        float4 x2 = xp[2 * 4 + q];
        float4 x3 = xp[3 * 4 + q];
        float xc0[4] = {x0.x, x0.y, x0.z, x0.w};
        float xc1[4] = {x1.x, x1.y, x1.z, x1.w};
        float xc2[4] = {x2.x, x2.y, x2.z, x2.w};
        float xc3[4] = {x3.x, x3.y, x3.z, x3.w};
        unsigned b0 = 0, b1 = 0, b2 = 0, b3 = 0;
        unsigned mask = 1u;
#pragma unroll 4
        for (int o = 0; o < 32; o++) {
            float4 pA = *(const float4*)&sp.c0[o][0];
            float4 pB = *(const float4*)&sp.c0[o][4];
#pragma unroll
            for (int j = 0; j < 4; j++) {
                float y = pA.x * xc0[j];
                y = fmaf(pA.y, xc1[j], y);
                y = fmaf(pA.z, xc2[j], y);
                y = fmaf(pA.w, xc3[j], y);
                float t1 = y + pB.x;
                float t2 = t1 - pB.y;
                float v = fmaf(t2, pB.z, pB.w);
                unsigned bit = (v >= 0.f) ? mask : 0u;
                if (j == 0) b0 |= bit;
                else if (j == 1) b1 |= bit;
                else if (j == 2) b2 |= bit;
                else b3 |= bit;
            }
            mask <<= 1;
        }
        u0[q * 4 + 0] = b0; u0[q * 4 + 1] = b1;
        u0[q * 4 + 2] = b2; u0[q * 4 + 3] = b3;
    }

    // ---- block 0: input = s0 (single plane) -----------------------------
    unsigned uc[16], un[16];
#pragma unroll
    for (int l = 0; l < 16; l++) un[l] = 0;
    {
        unsigned mask = 1u;
#pragma unroll 2
        for (int o = 0; o < 32; o++) {
            unsigned w0 = sp.Wb[0][o][0], w1 = sp.Wb[0][o][1], w2 = sp.Wb[0][o][2];
            int pmi = sp.PmI[0][o], pme = sp.PmE[0][o];
            {
                int P = __popc(u0[0] ^ w1) + __popc(u0[1] ^ w2);
                if (P <= pme) un[0] |= mask;
            }
#pragma unroll
            for (int l = 1; l < 15; l++) {
                int P = __popc(u0[l - 1] ^ w0) + __popc(u0[l] ^ w1) + __popc(u0[l + 1] ^ w2);
                if (P <= pmi) un[l] |= mask;
            }
            {
                int P = __popc(u0[14] ^ w0) + __popc(u0[15] ^ w1);
                if (P <= pme) un[15] |= mask;
            }
            mask <<= 1;
        }
    }
#pragma unroll
    for (int l = 0; l < 16; l++) uc[l] = un[l];

    // ---- blocks 1..3: two planes via carry-save popcount ----------------
    // popc(u0^w) + popc(uc^w) = popc(u0^uc) + 2*popc((u0^w)&(uc^w))
#pragma unroll 1
    for (int i = 1; i < 4; i++) {
        int DI[16];   // per-position precomputed plane-difference popcounts
        {
            int D[16];
#pragma unroll
            for (int l = 0; l < 16; l++) D[l] = __popc(u0[l] ^ uc[l]);
            DI[0] = D[0] + D[1];
#pragma unroll
            for (int l = 1; l < 15; l++) DI[l] = D[l - 1] + D[l] + D[l + 1];
            DI[15] = D[14] + D[15];
        }
#pragma unroll
        for (int l = 0; l < 16; l++) un[l] = 0;
        unsigned mask = 1u;
#pragma unroll 2
        for (int o = 0; o < 32; o++) {
            unsigned w0 = sp.Wb[i][o][0], w1 = sp.Wb[i][o][1], w2 = sp.Wb[i][o][2];
            int pmi = sp.PmI[i][o], pme = sp.PmE[i][o];
            {
                int Pc = __popc((u0[0] ^ w1) & (uc[0] ^ w1))
                       + __popc((u0[1] ^ w2) & (uc[1] ^ w2));
                if (2 * Pc + DI[0] <= pme) un[0] |= mask;
            }
#pragma unroll
            for (int l = 1; l < 15; l++) {
                int Pc = __popc((u0[l - 1] ^ w0) & (uc[l - 1] ^ w0))
                       + __popc((u0[l]     ^ w1) & (uc[l]     ^ w1))
                       + __popc((u0[l + 1] ^ w2) & (uc[l + 1] ^ w2));
                if (2 * Pc + DI[l] <= pmi) un[l] |= mask;
            }
            {
                int Pc = __popc((u0[14] ^ w0) & (uc[14] ^ w0))
                       + __popc((u0[15] ^ w1) & (uc[15] ^ w1));
                if (2 * Pc + DI[15] <= pme) un[15] |= mask;
            }
            mask <<= 1;
        }
#pragma unroll
        for (int l = 0; l < 16; l++) uc[l] = un[l];
    }

    // ---- fc1: two 512-bit planes via carry-save --------------------------
    unsigned hb0 = 0, hb1 = 0;
    {
        int Dsum = 0;
#pragma unroll
        for (int l = 0; l < 16; l++) Dsum += __popc(u0[l] ^ uc[l]);

        unsigned mask = 1u;
#pragma unroll 2
        for (int o = 0; o < 32; o++) {
            int Pc = 0;
#pragma unroll
            for (int l = 0; l < 16; l++) {
                unsigned w = sp.W1[o][l];
                Pc += __popc((u0[l] ^ w) & (uc[l] ^ w));
            }
            if (2 * Pc + Dsum <= sp.P5[o]) hb0 |= mask;
            mask <<= 1;
        }
        mask = 1u;
#pragma unroll 2
        for (int o = 32; o < 64; o++) {
            int Pc = 0;
#pragma unroll
            for (int l = 0; l < 16; l++) {
                unsigned w = sp.W1[o][l];
                Pc += __popc((u0[l] ^ w) & (uc[l] ^ w));
            }
            if (2 * Pc + Dsum <= sp.P5[o]) hb1 |= mask;
            mask <<= 1;
        }
    }

    // ---- fc2 -------------------------------------------------------------
    unsigned gb0 = 0, gb1 = 0;
    {
        unsigned mask = 1u;
#pragma unroll 4
        for (int o = 0; o < 32; o++) {
            int P = __popc(hb0 ^ sp.W2[o][0]) + __popc(hb1 ^ sp.W2[o][1]);
            if (P <= sp.P6[o]) gb0 |= mask;
            mask <<= 1;
        }
        mask = 1u;
#pragma unroll 4
        for (int o = 32; o < 64; o++) {
            int P = __popc(hb0 ^ sp.W2[o][0]) + __popc(hb1 ^ sp.W2[o][1]);
            if (P <= sp.P6[o]) gb1 |= mask;
            mask <<= 1;
        }
    }

    // ---- fc3 + sigmoid (LUT) ----------------------------------------------
    int p3 = __popc(gb0 ^ sp.W3[0]) + __popc(gb1 ^ sp.W3[1]);
    out[b] = sp.sig[p3];
}

extern "C" void kernel_launch(void* const* d_in, const int* in_sizes, int n_in,
                              void* d_out, int out_size)
{
    const float* x       = (const float*)d_in[0];
    const float* conv0_w = (const float*)d_in[1];
    const float* conv0_b = (const float*)d_in[2];
    const float* bn0_g   = (const float*)d_in[3];
    const float* bn0_b   = (const float*)d_in[4];
    const float* bn0_m   = (const float*)d_in[5];
    const float* bn0_v   = (const float*)d_in[6];
    const float* convs_w = (const float*)d_in[7];
    const float* convs_b = (const float*)d_in[8];
    const float* bns_g   = (const float*)d_in[9];
    const float* bns_b   = (const float*)d_in[10];
    const float* bns_m   = (const float*)d_in[11];
    const float* bns_v   = (const float*)d_in[12];
    const float* fc1_w   = (const float*)d_in[13];
    const float* fc1_b   = (const float*)d_in[14];
    const float* bn5_g   = (const float*)d_in[15];
    const float* bn5_b   = (const float*)d_in[16];
    const float* bn5_m   = (const float*)d_in[17];
    const float* bn5_v   = (const float*)d_in[18];
    const float* fc2_w   = (const float*)d_in[19];
    const float* fc2_b   = (const float*)d_in[20];
    const float* bn6_g   = (const float*)d_in[21];
    const float* bn6_b   = (const float*)d_in[22];
    const float* bn6_m   = (const float*)d_in[23];
    const float* bn6_v   = (const float*)d_in[24];
    const float* fc3_w   = (const float*)d_in[25];
    const float* fc3_b   = (const float*)d_in[26];

    int B = in_sizes[0] / 64;   // (B, 4, 16)
    float* out = (float*)d_out;

    prep_kernel<<<1, 256>>>(conv0_w, conv0_b, bn0_g, bn0_b, bn0_m, bn0_v,
                            convs_w, convs_b, bns_g, bns_b, bns_m, bns_v,
                            fc1_w, fc1_b, bn5_g, bn5_b, bn5_m, bn5_v,
                            fc2_w, fc2_b, bn6_g, bn6_b, bn6_m, bn6_v,
                            fc3_w, fc3_b);

    int blocks = (B + NT - 1) / NT;
    bnn_kernel<<<blocks, NT>>>(x, out, B);
}

// round 3
// speedup vs baseline: 1.6494x; 1.1009x over previous
#include <cuda_runtime.h>
#include <math.h>

// ---------------------------------------------------------------------------
// Binarized network, fully fused. v3:
//  - 2 lanes per batch element (positions 0-7 / 8-15) -> 4096 warps (2x occ)
//  - phantom-zero edge words + precomputed adjusted edge thresholds keep the
//    conv loops fully uniform across the lane pair (no divergence)
//  - carry-save popcount for all two-plane dots (exact integer identity)
// ---------------------------------------------------------------------------

struct Params {
    float    c0[32][8];      // per out-ch: s0..s3, conv_b, bn_m, bn_scale, bn_b
    unsigned Wb[4][32][3];   // conv block weight bits (bit c)
    int      thrI[4][32];    // interior threshold  (P <= thr -> +1)
    int      thrL[4][32];    // left-edge  threshold, phantom-adjusted
    int      thrR[4][32];    // right-edge threshold, phantom-adjusted
    unsigned W1[64][16];     // fc1 weight bits, word l, bit c (f idx = c*16+l)
    int      P5[64];
    unsigned W2[64][2];
    int      P6[64];
    unsigned W3[2];
    float    sig[65];        // sigmoid(64-2p + fc3_b)
};

__device__ Params g_p;

__device__ __forceinline__ float bnval(float z, float cb, float m, float sc, float bb) {
    float t1 = z + cb;
    float t2 = t1 - m;
    return fmaf(t2, sc, bb);
}

__global__ void prep_kernel(
    const float* conv0_w, const float* conv0_b,
    const float* bn0_g, const float* bn0_b, const float* bn0_m, const float* bn0_v,
    const float* convs_w, const float* convs_b,
    const float* bns_g, const float* bns_b, const float* bns_m, const float* bns_v,
    const float* fc1_w, const float* fc1_b,
    const float* bn5_g, const float* bn5_b, const float* bn5_m, const float* bn5_v,
    const float* fc2_w, const float* fc2_b,
    const float* bn6_g, const float* bn6_b, const float* bn6_m, const float* bn6_v,
    const float* fc3_w, const float* fc3_b)
{
    const int t = threadIdx.x;
    const int nt = blockDim.x;

    for (int o = t; o < 32; o += nt) {
        for (int c = 0; c < 4; c++)
            g_p.c0[o][c] = (conv0_w[o * 4 + c] >= 0.f) ? 1.f : -1.f;
        float sc = __fdiv_rn(bn0_g[o], __fsqrt_rn(bn0_v[o] + 0.01f));
        g_p.c0[o][4] = conv0_b[o];
        g_p.c0[o][5] = bn0_m[o];
        g_p.c0[o][6] = sc;
        g_p.c0[o][7] = bn0_b[o];
    }

    for (int idx = t; idx < 4 * 32 * 3; idx += nt) {
        int k = idx % 3, o = (idx / 3) % 32, i = idx / 96;
        unsigned w = 0;
        for (int c = 0; c < 32; c++)
            if (convs_w[((i * 32 + o) * 32 + c) * 3 + k] >= 0.f) w |= 1u << c;
        g_p.Wb[i][o][k] = w;
    }
    __syncthreads();   // Wb needed below for threshold adjustment

    for (int idx = t; idx < 128; idx += nt) {
        int i = idx / 32, o = idx % 32;
        int oi = i * 32 + o;
        float cb = convs_b[oi], m = bns_m[oi], bb = bns_b[oi];
        float sc = __fdiv_rn(bns_g[oi], __fsqrt_rn(bns_v[oi] + 0.01f));
        int Ci = (i == 0) ? 96 : 192;   // planes * 32 * 3
        int Ce = (i == 0) ? 64 : 128;   // planes * 32 * 2
        int mult = (i == 0) ? 1 : 2;    // planes
        int zth = Ci + 4;
        for (int z = -(Ci + 2); z <= Ci + 2; z += 2)
            if (bnval((float)z, cb, m, sc, bb) >= 0.f) { zth = z; break; }
        int pmi = (Ci - zth) / 2;
        int pme = (Ce - zth) / 2;
        g_p.thrI[i][o] = pmi;
        g_p.thrL[i][o] = pme + mult * __popc(g_p.Wb[i][o][0]);
        g_p.thrR[i][o] = pme + mult * __popc(g_p.Wb[i][o][2]);
    }

    for (int idx = t; idx < 64 * 16; idx += nt) {
        int l = idx % 16, o = idx / 16;
        unsigned w = 0;
        for (int c = 0; c < 32; c++)
            if (fc1_w[o * 512 + c * 16 + l] >= 0.f) w |= 1u << c;
        g_p.W1[o][l] = w;
    }
    for (int o = t; o < 64; o += nt) {
        float cb = fc1_b[o], m = bn5_m[o], bb = bn5_b[o];
        float sc = __fdiv_rn(bn5_g[o], __fsqrt_rn(bn5_v[o] + 0.01f));
        int zth = 1028;
        for (int z = -1026; z <= 1026; z += 2)
            if (bnval((float)z, cb, m, sc, bb) >= 0.f) { zth = z; break; }
        g_p.P5[o] = (1024 - zth) / 2;
    }

    for (int idx = t; idx < 128; idx += nt) {
        int j = idx % 2, o = idx / 2;
        unsigned w = 0;
        for (int c = 0; c < 32; c++)
            if (fc2_w[o * 64 + j * 32 + c] >= 0.f) w |= 1u << c;
        g_p.W2[o][j] = w;
    }
    for (int o = t; o < 64; o += nt) {
        float cb = fc2_b[o], m = bn6_m[o], bb = bn6_b[o];
        float sc = __fdiv_rn(bn6_g[o], __fsqrt_rn(bn6_v[o] + 0.01f));
        int zth = 68;
        for (int z = -66; z <= 66; z += 2)
            if (bnval((float)z, cb, m, sc, bb) >= 0.f) { zth = z; break; }
        g_p.P6[o] = (64 - zth) / 2;
    }

    if (t < 2) {
        unsigned w = 0;
        for (int c = 0; c < 32; c++)
            if (fc3_w[t * 32 + c] >= 0.f) w |= 1u << c;
        g_p.W3[t] = w;
    }
    for (int p = t; p < 65; p += nt) {
        float d = (float)(64 - 2 * p) + fc3_b[0];
        g_p.sig[p] = 1.f / (1.f + expf(-d));
    }
}

#define NT 128

__global__ __launch_bounds__(NT, 6) void bnn_kernel(
    const float* __restrict__ x, float* __restrict__ out, int B)
{
    __shared__ Params sp;
    {
        const int n = (int)(sizeof(Params) / 4);
        const int* src = (const int*)&g_p;
        int* dst = (int*)&sp;
        for (int i = threadIdx.x; i < n; i += NT) dst[i] = src[i];
    }
    __syncthreads();

    int gt = blockIdx.x * NT + threadIdx.x;
    int b = gt >> 1;
    int half = gt & 1;            // 0: positions 0-7, 1: positions 8-15
    if (b >= B) return;
    const bool lo = (half == 0);

    // ---- conv0 + bn0 + sign for my 8 positions -> v0[1..8] ---------------
    unsigned v0[10];
#pragma unroll
    for (int k = 0; k < 10; k++) v0[k] = 0;

    {
        float xc[4][8];
        const float4* xp = (const float4*)(x + (size_t)b * 64 + half * 8);
#pragma unroll
        for (int c = 0; c < 4; c++) {
            float4 a = xp[c * 4 + 0];
            float4 d = xp[c * 4 + 1];
            xc[c][0] = a.x; xc[c][1] = a.y; xc[c][2] = a.z; xc[c][3] = a.w;
            xc[c][4] = d.x; xc[c][5] = d.y; xc[c][6] = d.z; xc[c][7] = d.w;
        }
        unsigned mask = 1u;
#pragma unroll 4
        for (int o = 0; o < 32; o++) {
            float4 pA = *(const float4*)&sp.c0[o][0];
            float4 pB = *(const float4*)&sp.c0[o][4];
#pragma unroll
            for (int j = 0; j < 8; j++) {
                float y = pA.x * xc[0][j];
                y = fmaf(pA.y, xc[1][j], y);
                y = fmaf(pA.z, xc[2][j], y);
                y = fmaf(pA.w, xc[3][j], y);
                float t1 = y + pB.x;
                float t2 = t1 - pB.y;
                float v = fmaf(t2, pB.z, pB.w);
                if (v >= 0.f) v0[j + 1] |= mask;
            }
            mask <<= 1;
        }
    }

    // halo exchange for s0 plane (phantom zeros at the outer edges)
    {
        unsigned send = lo ? v0[8] : v0[1];
        unsigned recv = __shfl_xor_sync(0xffffffffu, send, 1);
        v0[0] = lo ? 0u : recv;
        v0[9] = lo ? recv : 0u;
    }

    // ---- block 0: single plane ------------------------------------------
    unsigned vc[10], un[8];
    vc[0] = 0; vc[9] = 0;
#pragma unroll
    for (int j = 0; j < 8; j++) un[j] = 0;
    {
        unsigned mask = 1u;
#pragma unroll 4
        for (int o = 0; o < 32; o++) {
            unsigned w0 = sp.Wb[0][o][0], w1 = sp.Wb[0][o][1], w2 = sp.Wb[0][o][2];
            int thrI = sp.thrI[0][o];
            int t0 = lo ? sp.thrL[0][o] : thrI;
            int t7 = lo ? thrI : sp.thrR[0][o];
#pragma unroll
            for (int j = 0; j < 8; j++) {
                int P = __popc(v0[j] ^ w0) + __popc(v0[j + 1] ^ w1) + __popc(v0[j + 2] ^ w2);
                int thr = (j == 0) ? t0 : (j == 7) ? t7 : thrI;
                if (P <= thr) un[j] |= mask;
            }
            mask <<= 1;
        }
    }
#pragma unroll
    for (int j = 0; j < 8; j++) vc[j + 1] = un[j];

    // ---- blocks 1..3: two planes, carry-save ------------------------------
#pragma unroll 1
    for (int i = 1; i < 4; i++) {
        // halo exchange for current plane
        {
            unsigned send = lo ? vc[8] : vc[1];
            unsigned recv = __shfl_xor_sync(0xffffffffu, send, 1);
            vc[0] = lo ? 0u : recv;
            vc[9] = lo ? recv : 0u;
        }
        int DI[8];
        {
            int D[10];
#pragma unroll
            for (int k = 0; k < 10; k++) D[k] = __popc(v0[k] ^ vc[k]);
#pragma unroll
            for (int j = 0; j < 8; j++) DI[j] = D[j] + D[j + 1] + D[j + 2];
        }
#pragma unroll
        for (int j = 0; j < 8; j++) un[j] = 0;
        unsigned mask = 1u;
#pragma unroll 4
        for (int o = 0; o < 32; o++) {
            unsigned w0 = sp.Wb[i][o][0], w1 = sp.Wb[i][o][1], w2 = sp.Wb[i][o][2];
            int thrI = sp.thrI[i][o];
            int t0 = lo ? sp.thrL[i][o] : thrI;
            int t7 = lo ? thrI : sp.thrR[i][o];
#pragma unroll
            for (int j = 0; j < 8; j++) {
                int Pc = __popc((v0[j]     ^ w0) & (vc[j]     ^ w0))
                       + __popc((v0[j + 1] ^ w1) & (vc[j + 1] ^ w1))
                       + __popc((v0[j + 2] ^ w2) & (vc[j + 2] ^ w2));
                int thr = (j == 0) ? t0 : (j == 7) ? t7 : thrI;
                if (2 * Pc + DI[j] <= thr) un[j] |= mask;
            }
            mask <<= 1;
        }
#pragma unroll
        for (int j = 0; j < 8; j++) vc[j + 1] = un[j];
    }

    // ---- assemble full 16-word planes (16 shuffles) ------------------------
    unsigned fu0[16], fuc[16];
#pragma unroll
    for (int j = 0; j < 8; j++) {
        unsigned o0 = __shfl_xor_sync(0xffffffffu, v0[j + 1], 1);
        unsigned oc = __shfl_xor_sync(0xffffffffu, vc[j + 1], 1);
        fu0[j]     = lo ? v0[j + 1] : o0;
        fu0[j + 8] = lo ? o0        : v0[j + 1];
        fuc[j]     = lo ? vc[j + 1] : oc;
        fuc[j + 8] = lo ? oc        : vc[j + 1];
    }

    // ---- fc1: 32 outputs per lane, carry-save ------------------------------
    int Dsum = 0;
#pragma unroll
    for (int l = 0; l < 16; l++) Dsum += __popc(fu0[l] ^ fuc[l]);

    const int obase = half * 32;
    unsigned hb = 0;
    {
        unsigned mask = 1u;
#pragma unroll 2
        for (int oo = 0; oo < 32; oo++) {
            int o = obase + oo;
            int Pc = 0;
#pragma unroll
            for (int l = 0; l < 16; l++) {
                unsigned w = sp.W1[o][l];
                Pc += __popc((fu0[l] ^ w) & (fuc[l] ^ w));
            }
            if (2 * Pc + Dsum <= sp.P5[o]) hb |= mask;
            mask <<= 1;
        }
    }
    unsigned hbo = __shfl_xor_sync(0xffffffffu, hb, 1);
    unsigned hb0 = lo ? hb : hbo;
    unsigned hb1 = lo ? hbo : hb;

    // ---- fc2: 32 outputs per lane ------------------------------------------
    unsigned gb = 0;
    {
        unsigned mask = 1u;
#pragma unroll 4
        for (int oo = 0; oo < 32; oo++) {
            int o = obase + oo;
            int P = __popc(hb0 ^ sp.W2[o][0]) + __popc(hb1 ^ sp.W2[o][1]);
            if (P <= sp.P6[o]) gb |= mask;
            mask <<= 1;
        }
    }
    unsigned gbo = __shfl_xor_sync(0xffffffffu, gb, 1);

    // ---- fc3 + sigmoid LUT, even lane writes -------------------------------
    if (lo) {
        int p3 = __popc(gb ^ sp.W3[0]) + __popc(gbo ^ sp.W3[1]);
        out[b] = sp.sig[p3];
    }
}

extern "C" void kernel_launch(void* const* d_in, const int* in_sizes, int n_in,
                              void* d_out, int out_size)
{
    const float* x       = (const float*)d_in[0];
    const float* conv0_w = (const float*)d_in[1];
    const float* conv0_b = (const float*)d_in[2];
    const float* bn0_g   = (const float*)d_in[3];
    const float* bn0_b   = (const float*)d_in[4];
    const float* bn0_m   = (const float*)d_in[5];
    const float* bn0_v   = (const float*)d_in[6];
    const float* convs_w = (const float*)d_in[7];
    const float* convs_b = (const float*)d_in[8];
    const float* bns_g   = (const float*)d_in[9];
    const float* bns_b   = (const float*)d_in[10];
    const float* bns_m   = (const float*)d_in[11];
    const float* bns_v   = (const float*)d_in[12];
    const float* fc1_w   = (const float*)d_in[13];
    const float* fc1_b   = (const float*)d_in[14];
    const float* bn5_g   = (const float*)d_in[15];
    const float* bn5_b   = (const float*)d_in[16];
    const float* bn5_m   = (const float*)d_in[17];
    const float* bn5_v   = (const float*)d_in[18];
    const float* fc2_w   = (const float*)d_in[19];
    const float* fc2_b   = (const float*)d_in[20];
    const float* bn6_g   = (const float*)d_in[21];
    const float* bn6_b   = (const float*)d_in[22];
    const float* bn6_m   = (const float*)d_in[23];
    const float* bn6_v   = (const float*)d_in[24];
    const float* fc3_w   = (const float*)d_in[25];
    const float* fc3_b   = (const float*)d_in[26];

    int B = in_sizes[0] / 64;   // (B, 4, 16)
    float* out = (float*)d_out;

    prep_kernel<<<1, 256>>>(conv0_w, conv0_b, bn0_g, bn0_b, bn0_m, bn0_v,
                            convs_w, convs_b, bns_g, bns_b, bns_m, bns_v,
                            fc1_w, fc1_b, bn5_g, bn5_b, bn5_m, bn5_v,
                            fc2_w, fc2_b, bn6_g, bn6_b, bn6_m, bn6_v,
                            fc3_w, fc3_b);

    long long totalThreads = 2LL * B;
    int blocks = (int)((totalThreads + NT - 1) / NT);
    bnn_kernel<<<blocks, NT>>>(x, out, B);
}

// round 4
// speedup vs baseline: 1.7692x; 1.0726x over previous
#include <cuda_runtime.h>
#include <math.h>

// ---------------------------------------------------------------------------
// Binarized network, fully fused. v4:
//  - 4 lanes per batch element (4 positions each) -> 8192 warps
//  - warp-uniform tables in __constant__ (LDCU path), divergent tables in smem
//  - strided output assignment o = q + 4*oo for fc1/fc2 (bank-conflict-free),
//    with the bit permutation folded into W2/W3 at prep time
//  - carry-save popcount, phantom-edge thresholds, binary-search thresholds
// ---------------------------------------------------------------------------

struct CP {                  // warp-uniform -> __constant__
    float    c0[32][8];      // per out-ch: s0..s3, conv_b, bn_m, bn_scale, bn_b
    unsigned Wb[4][32][3];   // conv block weight bits (bit c)
    int      thrI[4][32];
    int      thrL[4][32];    // phantom-adjusted left edge
    int      thrR[4][32];    // phantom-adjusted right edge
};
struct SP {                  // per-lane divergent -> shared
    unsigned W1p[64][17];    // fc1 weights, row stride 17 (bank spread)
    int      P5[64];
    unsigned W2p[64][2];     // fc2 weights, h-bit-permuted
    int      P6[64];
    unsigned W3p[2];         // fc3 weights, permuted
    float    sig[65];
};

__device__ CP g_cp;
__device__ SP g_sp;
__constant__ CP c_cp;

__device__ __forceinline__ float bnval(float z, float cb, float m, float sc, float bb) {
    float t1 = z + cb;
    float t2 = t1 - m;
    return fmaf(t2, sc, bb);
}

// first even z in [zmin, zmax] with bnval >= 0 (monotone); zmax+2 if none
__device__ int first_nonneg_z(int zmin, int zmax, float cb, float m, float sc, float bb) {
    int lo = zmin >> 1, hi = zmax >> 1;   // even -> exact
    int ans = hi + 1;
    while (lo <= hi) {
        int mid = lo + ((hi - lo) >> 1);
        if (bnval((float)(2 * mid), cb, m, sc, bb) >= 0.f) { ans = mid; hi = mid - 1; }
        else lo = mid + 1;
    }
    return 2 * ans;
}

__device__ __forceinline__ int permOrig(int w, int t) {
    // assembled word w bit t -> original output index
    if (w == 0) return (t < 16) ? 4 * t : 4 * (t - 16) + 1;
    else        return (t < 16) ? 4 * t + 2 : 4 * (t - 16) + 3;
}

__global__ void prep_kernel(
    const float* conv0_w, const float* conv0_b,
    const float* bn0_g, const float* bn0_b, const float* bn0_m, const float* bn0_v,
    const float* convs_w, const float* convs_b,
    const float* bns_g, const float* bns_b, const float* bns_m, const float* bns_v,
    const float* fc1_w, const float* fc1_b,
    const float* bn5_g, const float* bn5_b, const float* bn5_m, const float* bn5_v,
    const float* fc2_w, const float* fc2_b,
    const float* bn6_g, const float* bn6_b, const float* bn6_m, const float* bn6_v,
    const float* fc3_w, const float* fc3_b)
{
    const int t = threadIdx.x;
    const int nt = blockDim.x;

    for (int o = t; o < 32; o += nt) {
        for (int c = 0; c < 4; c++)
            g_cp.c0[o][c] = (conv0_w[o * 4 + c] >= 0.f) ? 1.f : -1.f;
        float sc = __fdiv_rn(bn0_g[o], __fsqrt_rn(bn0_v[o] + 0.01f));
        g_cp.c0[o][4] = conv0_b[o];
        g_cp.c0[o][5] = bn0_m[o];
        g_cp.c0[o][6] = sc;
        g_cp.c0[o][7] = bn0_b[o];
    }

    for (int idx = t; idx < 4 * 32 * 3; idx += nt) {
        int k = idx % 3, o = (idx / 3) % 32, i = idx / 96;
        unsigned w = 0;
        for (int c = 0; c < 32; c++)
            if (convs_w[((i * 32 + o) * 32 + c) * 3 + k] >= 0.f) w |= 1u << c;
        g_cp.Wb[i][o][k] = w;
    }
    __syncthreads();   // Wb needed for edge threshold adjustment

    for (int idx = t; idx < 128; idx += nt) {
        int i = idx / 32, o = idx % 32;
        int oi = i * 32 + o;
        float cb = convs_b[oi], m = bns_m[oi], bb = bns_b[oi];
        float sc = __fdiv_rn(bns_g[oi], __fsqrt_rn(bns_v[oi] + 0.01f));
        int Ci = (i == 0) ? 96 : 192;   // planes*32*3
        int Ce = (i == 0) ? 64 : 128;   // planes*32*2
        int mult = (i == 0) ? 1 : 2;
        int zth = first_nonneg_z(-(Ci + 2), Ci + 2, cb, m, sc, bb);
        int pmi = (Ci - zth) / 2;
        int pme = (Ce - zth) / 2;
        g_cp.thrI[i][o] = pmi;
        g_cp.thrL[i][o] = pme + mult * __popc(g_cp.Wb[i][o][0]);
        g_cp.thrR[i][o] = pme + mult * __popc(g_cp.Wb[i][o][2]);
    }

    for (int idx = t; idx < 64 * 16; idx += nt) {
        int l = idx % 16, o = idx / 16;
        unsigned w = 0;
        for (int c = 0; c < 32; c++)
            if (fc1_w[o * 512 + c * 16 + l] >= 0.f) w |= 1u << c;
        g_sp.W1p[o][l] = w;
    }
    for (int o = t; o < 64; o += nt) {
        g_sp.W1p[o][16] = 0;   // pad
        float cb = fc1_b[o], m = bn5_m[o], bb = bn5_b[o];
        float sc = __fdiv_rn(bn5_g[o], __fsqrt_rn(bn5_v[o] + 0.01f));
        int zth = first_nonneg_z(-1026, 1026, cb, m, sc, bb);
        g_sp.P5[o] = (1024 - zth) / 2;
    }

    for (int idx = t; idx < 128; idx += nt) {
        int w = idx & 1, o = idx >> 1;
        unsigned r = 0;
        for (int tb = 0; tb < 32; tb++)
            if (fc2_w[o * 64 + permOrig(w, tb)] >= 0.f) r |= 1u << tb;
        g_sp.W2p[o][w] = r;
    }
    for (int o = t; o < 64; o += nt) {
        float cb = fc2_b[o], m = bn6_m[o], bb = bn6_b[o];
        float sc = __fdiv_rn(bn6_g[o], __fsqrt_rn(bn6_v[o] + 0.01f));
        int zth = first_nonneg_z(-66, 66, cb, m, sc, bb);
        g_sp.P6[o] = (64 - zth) / 2;
    }

    if (t < 2) {
        unsigned r = 0;
        for (int tb = 0; tb < 32; tb++)
            if (fc3_w[permOrig(t, tb)] >= 0.f) r |= 1u << tb;
        g_sp.W3p[t] = r;
    }
    for (int p = t; p < 65; p += nt) {
        float d = (float)(64 - 2 * p) + fc3_b[0];
        g_sp.sig[p] = 1.f / (1.f + expf(-d));
    }
}

#define NT 128

__global__ __launch_bounds__(NT, 8) void bnn_kernel(
    const float* __restrict__ x, float* __restrict__ out, int B)
{
    __shared__ SP sp;
    __shared__ unsigned buf[32][33];   // per 4-lane group: 16 u0 words + 16 uc words
    {
        const int n = (int)(sizeof(SP) / 4);
        const int* src = (const int*)&g_sp;
        int* dst = (int*)&sp;
        for (int i = threadIdx.x; i < n; i += NT) dst[i] = src[i];
    }
    __syncthreads();

    int gt = blockIdx.x * NT + threadIdx.x;
    int e = gt >> 2;
    int q = gt & 3;                 // quarter: positions 4q..4q+3
    if (e >= B) return;
    const int grp = threadIdx.x >> 2;
    const unsigned FULL = 0xffffffffu;

    // ---- conv0 + bn0 + sign -> v0[1..4] ----------------------------------
    unsigned v0[6];
#pragma unroll
    for (int k = 0; k < 6; k++) v0[k] = 0;
    {
        const float* xb = x + (size_t)e * 64 + q * 4;
        float4 c0v = *(const float4*)(xb + 0);
        float4 c1v = *(const float4*)(xb + 16);
        float4 c2v = *(const float4*)(xb + 32);
        float4 c3v = *(const float4*)(xb + 48);
        float a0[4] = {c0v.x, c0v.y, c0v.z, c0v.w};
        float a1[4] = {c1v.x, c1v.y, c1v.z, c1v.w};
        float a2[4] = {c2v.x, c2v.y, c2v.z, c2v.w};
        float a3[4] = {c3v.x, c3v.y, c3v.z, c3v.w};
        unsigned mask = 1u;
#pragma unroll 4
        for (int o = 0; o < 32; o++) {
            float4 pA = *(const float4*)&c_cp.c0[o][0];
            float4 pB = *(const float4*)&c_cp.c0[o][4];
#pragma unroll
            for (int j = 0; j < 4; j++) {
                float y = pA.x * a0[j];
                y = fmaf(pA.y, a1[j], y);
                y = fmaf(pA.z, a2[j], y);
                y = fmaf(pA.w, a3[j], y);
                float t1 = y + pB.x;
                float t2 = t1 - pB.y;
                float v = fmaf(t2, pB.z, pB.w);
                if (v >= 0.f) v0[j + 1] |= mask;
            }
            mask <<= 1;
        }
    }
    // halo for s0 plane
    {
        unsigned up = __shfl_up_sync(FULL, v0[4], 1);
        unsigned dn = __shfl_down_sync(FULL, v0[1], 1);
        v0[0] = (q == 0) ? 0u : up;
        v0[5] = (q == 3) ? 0u : dn;
    }

    // ---- block 0: single plane -------------------------------------------
    unsigned vc[6], un[4];
    vc[0] = 0; vc[5] = 0;
#pragma unroll
    for (int j = 0; j < 4; j++) un[j] = 0;
    {
        unsigned mask = 1u;
#pragma unroll 4
        for (int o = 0; o < 32; o++) {
            unsigned w0 = c_cp.Wb[0][o][0], w1 = c_cp.Wb[0][o][1], w2 = c_cp.Wb[0][o][2];
            int thrI = c_cp.thrI[0][o];
            int tf = (q == 0) ? c_cp.thrL[0][o] : thrI;
            int tl = (q == 3) ? c_cp.thrR[0][o] : thrI;
#pragma unroll
            for (int j = 0; j < 4; j++) {
                int P = __popc(v0[j] ^ w0) + __popc(v0[j + 1] ^ w1) + __popc(v0[j + 2] ^ w2);
                int thr = (j == 0) ? tf : (j == 3) ? tl : thrI;
                if (P <= thr) un[j] |= mask;
            }
            mask <<= 1;
        }
    }
#pragma unroll
    for (int j = 0; j < 4; j++) vc[j + 1] = un[j];

    // ---- blocks 1..3: two planes, carry-save -------------------------------
#pragma unroll 1
    for (int i = 1; i < 4; i++) {
        {
            unsigned up = __shfl_up_sync(FULL, vc[4], 1);
            unsigned dn = __shfl_down_sync(FULL, vc[1], 1);
            vc[0] = (q == 0) ? 0u : up;
            vc[5] = (q == 3) ? 0u : dn;
        }
        int DI[4];
        {
            int D[6];
#pragma unroll
            for (int k = 0; k < 6; k++) D[k] = __popc(v0[k] ^ vc[k]);
#pragma unroll
            for (int j = 0; j < 4; j++) DI[j] = D[j] + D[j + 1] + D[j + 2];
        }
#pragma unroll
        for (int j = 0; j < 4; j++) un[j] = 0;
        unsigned mask = 1u;
#pragma unroll 4
        for (int o = 0; o < 32; o++) {
            unsigned w0 = c_cp.Wb[i][o][0], w1 = c_cp.Wb[i][o][1], w2 = c_cp.Wb[i][o][2];
            int thrI = c_cp.thrI[i][o];
            int tf = (q == 0) ? c_cp.thrL[i][o] : thrI;
            int tl = (q == 3) ? c_cp.thrR[i][o] : thrI;
#pragma unroll
            for (int j = 0; j < 4; j++) {
                int Pc = __popc((v0[j]     ^ w0) & (vc[j]     ^ w0))
                       + __popc((v0[j + 1] ^ w1) & (vc[j + 1] ^ w1))
                       + __popc((v0[j + 2] ^ w2) & (vc[j + 2] ^ w2));
                int thr = (j == 0) ? tf : (j == 3) ? tl : thrI;
                if (2 * Pc + DI[j] <= thr) un[j] |= mask;
            }
            mask <<= 1;
        }
#pragma unroll
        for (int j = 0; j < 4; j++) vc[j + 1] = un[j];
    }

    // ---- stash planes for full-width fc1 -----------------------------------
#pragma unroll
    for (int j = 0; j < 4; j++) {
        buf[grp][4 * q + j]      = v0[j + 1];
        buf[grp][16 + 4 * q + j] = vc[j + 1];
    }
    __syncwarp();

    // Dsum over all 16 words (butterfly within the 4-lane group)
    int ds = 0;
#pragma unroll
    for (int j = 0; j < 4; j++) ds += __popc(v0[j + 1] ^ vc[j + 1]);
    ds += __shfl_xor_sync(FULL, ds, 1);
    ds += __shfl_xor_sync(FULL, ds, 2);

    unsigned f0[16], fp[16];
#pragma unroll
    for (int l = 0; l < 16; l++) {
        f0[l] = buf[grp][l];
        fp[l] = buf[grp][16 + l];
    }

    // ---- fc1: outputs o = q + 4*oo ------------------------------------------
    unsigned hb = 0;
#pragma unroll 2
    for (int oo = 0; oo < 16; oo++) {
        int o = q + 4 * oo;
        int Pc = 0;
#pragma unroll
        for (int l = 0; l < 16; l++) {
            unsigned w = sp.W1p[o][l];
            Pc += __popc((f0[l] ^ w) & (fp[l] ^ w));
        }
        if (2 * Pc + ds <= sp.P5[o]) hb |= 1u << oo;
    }
    // assemble permuted h words
    unsigned t1 = __shfl_xor_sync(FULL, hb, 1);
    unsigned pw = (q & 1) ? ((hb << 16) | t1) : ((t1 << 16) | hb);
    unsigned t2 = __shfl_xor_sync(FULL, pw, 2);
    unsigned hw0 = (q < 2) ? pw : t2;
    unsigned hw1 = (q < 2) ? t2 : pw;

    // ---- fc2: outputs o = q + 4*oo --------------------------------------------
    unsigned gb = 0;
#pragma unroll 4
    for (int oo = 0; oo < 16; oo++) {
        int o = q + 4 * oo;
        int P = __popc(hw0 ^ sp.W2p[o][0]) + __popc(hw1 ^ sp.W2p[o][1]);
        if (P <= sp.P6[o]) gb |= 1u << oo;
    }
    t1 = __shfl_xor_sync(FULL, gb, 1);
    pw = (q & 1) ? ((gb << 16) | t1) : ((t1 << 16) | gb);
    t2 = __shfl_xor_sync(FULL, pw, 2);
    unsigned gw0 = (q < 2) ? pw : t2;
    unsigned gw1 = (q < 2) ? t2 : pw;

    // ---- fc3 + sigmoid LUT ------------------------------------------------------
    if (q == 0) {
        int p3 = __popc(gw0 ^ sp.W3p[0]) + __popc(gw1 ^ sp.W3p[1]);
        out[e] = sp.sig[p3];
    }
}

extern "C" void kernel_launch(void* const* d_in, const int* in_sizes, int n_in,
                              void* d_out, int out_size)
{
    const float* x       = (const float*)d_in[0];
    const float* conv0_w = (const float*)d_in[1];
    const float* conv0_b = (const float*)d_in[2];
    const float* bn0_g   = (const float*)d_in[3];
    const float* bn0_b   = (const float*)d_in[4];
    const float* bn0_m   = (const float*)d_in[5];
    const float* bn0_v   = (const float*)d_in[6];
    const float* convs_w = (const float*)d_in[7];
    const float* convs_b = (const float*)d_in[8];
    const float* bns_g   = (const float*)d_in[9];
    const float* bns_b   = (const float*)d_in[10];
    const float* bns_m   = (const float*)d_in[11];
    const float* bns_v   = (const float*)d_in[12];
    const float* fc1_w   = (const float*)d_in[13];
    const float* fc1_b   = (const float*)d_in[14];
    const float* bn5_g   = (const float*)d_in[15];
    const float* bn5_b   = (const float*)d_in[16];
    const float* bn5_m   = (const float*)d_in[17];
    const float* bn5_v   = (const float*)d_in[18];
    const float* fc2_w   = (const float*)d_in[19];
    const float* fc2_b   = (const float*)d_in[20];
    const float* bn6_g   = (const float*)d_in[21];
    const float* bn6_b   = (const float*)d_in[22];
    const float* bn6_m   = (const float*)d_in[23];
    const float* bn6_v   = (const float*)d_in[24];
    const float* fc3_w   = (const float*)d_in[25];
    const float* fc3_b   = (const float*)d_in[26];

    int B = in_sizes[0] / 64;   // (B, 4, 16)
    float* out = (float*)d_out;

    prep_kernel<<<1, 256>>>(conv0_w, conv0_b, bn0_g, bn0_b, bn0_m, bn0_v,
                            convs_w, convs_b, bns_g, bns_b, bns_m, bns_v,
                            fc1_w, fc1_b, bn5_g, bn5_b, bn5_m, bn5_v,
                            fc2_w, fc2_b, bn6_g, bn6_b, bn6_m, bn6_v,
                            fc3_w, fc3_b);

    void* srcp = nullptr;
    cudaGetSymbolAddress(&srcp, g_cp);
    cudaMemcpyToSymbolAsync(c_cp, srcp, sizeof(CP), 0, cudaMemcpyDeviceToDevice, 0);

    long long totalThreads = 4LL * B;
    int blocks = (int)((totalThreads + NT - 1) / NT);
    bnn_kernel<<<blocks, NT>>>(x, out, B);
}

// round 5
// speedup vs baseline: 1.8211x; 1.0294x over previous
#include <cuda_runtime.h>
#include <math.h>

// ---------------------------------------------------------------------------
// Binarized network, fully fused. v5:
//  - forced single-LOP3 taps:  (v0^w)&(vc^w) == (v0^w) & ~(v0^vc),
//    with mb = xnor(v0,vc) precomputed per block (w-independent);
//    inline PTX lop3 immLut 0x28 guarantees 1 instruction per tap
//  - DI from popc(mb): DI[j] = 96 - (pm[j]+pm[j+1]+pm[j+2]); phantom edges
//    come out automatically (xnor(0,0) = ~0, pm = 32, D contribution 0)
//  - threshold edge-selects replaced by constant pointer tables per block
//  - fc1 weights + plane buffer accessed via LDS.128, conflict-free strides
// ---------------------------------------------------------------------------

struct __align__(16) CP {    // warp-uniform -> __constant__
    float    c0[32][8];      // per out-ch: s0..s3, conv_b, bn_m, bn_scale, bn_b
    unsigned Wb[4][32][3];   // conv block weight bits (bit c)
    int      thrA[4][2][32]; // [i][0][o]=thrI, [i][1][o]=thrL (left edge)
    int      thrB[4][2][32]; // [i][0][o]=thrI, [i][1][o]=thrR (right edge)
};
struct __align__(16) SP {    // per-lane divergent -> shared
    unsigned W1p[64][20];    // fc1 weights, row stride 20 (16B-aligned, bank-spread)
    int      P5[64];
    unsigned W2p[64][2];     // fc2 weights, h-bit-permuted (8B aligned)
    int      P6[64];
    unsigned W3p[2];
    float    sig[65];
};

__device__ CP g_cp;
__device__ SP g_sp;
__constant__ CP c_cp;

// (a^b)&c as a single LOP3 (immLut 0x28)
__device__ __forceinline__ unsigned xand(unsigned a, unsigned b, unsigned c) {
    unsigned r;
    asm("lop3.b32 %0, %1, %2, %3, 0x28;" : "=r"(r) : "r"(a), "r"(b), "r"(c));
    return r;
}

__device__ __forceinline__ float bnval(float z, float cb, float m, float sc, float bb) {
    float t1 = z + cb;
    float t2 = t1 - m;
    return fmaf(t2, sc, bb);
}

// first even z in [zmin, zmax] with bnval >= 0 (monotone); zmax+2 if none
__device__ int first_nonneg_z(int zmin, int zmax, float cb, float m, float sc, float bb) {
    int lo = zmin >> 1, hi = zmax >> 1;
    int ans = hi + 1;
    while (lo <= hi) {
        int mid = lo + ((hi - lo) >> 1);
        if (bnval((float)(2 * mid), cb, m, sc, bb) >= 0.f) { ans = mid; hi = mid - 1; }
        else lo = mid + 1;
    }
    return 2 * ans;
}

__device__ __forceinline__ int permOrig(int w, int t) {
    if (w == 0) return (t < 16) ? 4 * t : 4 * (t - 16) + 1;
    else        return (t < 16) ? 4 * t + 2 : 4 * (t - 16) + 3;
}

__global__ void prep_kernel(
    const float* conv0_w, const float* conv0_b,
    const float* bn0_g, const float* bn0_b, const float* bn0_m, const float* bn0_v,
    const float* convs_w, const float* convs_b,
    const float* bns_g, const float* bns_b, const float* bns_m, const float* bns_v,
    const float* fc1_w, const float* fc1_b,
    const float* bn5_g, const float* bn5_b, const float* bn5_m, const float* bn5_v,
    const float* fc2_w, const float* fc2_b,
    const float* bn6_g, const float* bn6_b, const float* bn6_m, const float* bn6_v,
    const float* fc3_w, const float* fc3_b)
{
    const int t = threadIdx.x;
    const int nt = blockDim.x;

    for (int o = t; o < 32; o += nt) {
        for (int c = 0; c < 4; c++)
            g_cp.c0[o][c] = (conv0_w[o * 4 + c] >= 0.f) ? 1.f : -1.f;
        float sc = __fdiv_rn(bn0_g[o], __fsqrt_rn(bn0_v[o] + 0.01f));
        g_cp.c0[o][4] = conv0_b[o];
        g_cp.c0[o][5] = bn0_m[o];
        g_cp.c0[o][6] = sc;
        g_cp.c0[o][7] = bn0_b[o];
    }

    for (int idx = t; idx < 4 * 32 * 3; idx += nt) {
        int k = idx % 3, o = (idx / 3) % 32, i = idx / 96;
        unsigned w = 0;
        for (int c = 0; c < 32; c++)
            if (convs_w[((i * 32 + o) * 32 + c) * 3 + k] >= 0.f) w |= 1u << c;
        g_cp.Wb[i][o][k] = w;
    }
    __syncthreads();   // Wb needed for edge threshold adjustment

    for (int idx = t; idx < 128; idx += nt) {
        int i = idx / 32, o = idx % 32;
        int oi = i * 32 + o;
        float cb = convs_b[oi], m = bns_m[oi], bb = bns_b[oi];
        float sc = __fdiv_rn(bns_g[oi], __fsqrt_rn(bns_v[oi] + 0.01f));
        int Ci = (i == 0) ? 96 : 192;   // planes*32*3
        int Ce = (i == 0) ? 64 : 128;   // planes*32*2
        int mult = (i == 0) ? 1 : 2;
        int zth = first_nonneg_z(-(Ci + 2), Ci + 2, cb, m, sc, bb);
        int pmi = (Ci - zth) / 2;
        int pme = (Ce - zth) / 2;
        g_cp.thrA[i][0][o] = pmi;
        g_cp.thrA[i][1][o] = pme + mult * __popc(g_cp.Wb[i][o][0]);
        g_cp.thrB[i][0][o] = pmi;
        g_cp.thrB[i][1][o] = pme + mult * __popc(g_cp.Wb[i][o][2]);
    }

    for (int idx = t; idx < 64 * 16; idx += nt) {
        int l = idx % 16, o = idx / 16;
        unsigned w = 0;
        for (int c = 0; c < 32; c++)
            if (fc1_w[o * 512 + c * 16 + l] >= 0.f) w |= 1u << c;
        g_sp.W1p[o][l] = w;
    }
    for (int o = t; o < 64; o += nt) {
        g_sp.W1p[o][16] = 0; g_sp.W1p[o][17] = 0;
        g_sp.W1p[o][18] = 0; g_sp.W1p[o][19] = 0;
        float cb = fc1_b[o], m = bn5_m[o], bb = bn5_b[o];
        float sc = __fdiv_rn(bn5_g[o], __fsqrt_rn(bn5_v[o] + 0.01f));
        int zth = first_nonneg_z(-1026, 1026, cb, m, sc, bb);
        g_sp.P5[o] = (1024 - zth) / 2;
    }

    for (int idx = t; idx < 128; idx += nt) {
        int w = idx & 1, o = idx >> 1;
        unsigned r = 0;
        for (int tb = 0; tb < 32; tb++)
            if (fc2_w[o * 64 + permOrig(w, tb)] >= 0.f) r |= 1u << tb;
        g_sp.W2p[o][w] = r;
    }
    for (int o = t; o < 64; o += nt) {
        float cb = fc2_b[o], m = bn6_m[o], bb = bn6_b[o];
        float sc = __fdiv_rn(bn6_g[o], __fsqrt_rn(bn6_v[o] + 0.01f));
        int zth = first_nonneg_z(-66, 66, cb, m, sc, bb);
        g_sp.P6[o] = (64 - zth) / 2;
    }

    if (t < 2) {
        unsigned r = 0;
        for (int tb = 0; tb < 32; tb++)
            if (fc3_w[permOrig(t, tb)] >= 0.f) r |= 1u << tb;
        g_sp.W3p[t] = r;
    }
    for (int p = t; p < 65; p += nt) {
        float d = (float)(64 - 2 * p) + fc3_b[0];
        g_sp.sig[p] = 1.f / (1.f + expf(-d));
    }
}

#define NT 128

__global__ __launch_bounds__(NT, 8) void bnn_kernel(
    const float* __restrict__ x, float* __restrict__ out, int B)
{
    __shared__ SP sp;
    __shared__ unsigned buf[32][36];   // [group][16 u0 | 16 uc | 4 pad], stride 36
    {
        const int n = (int)(sizeof(SP) / 4);
        const int* src = (const int*)&g_sp;
        int* dst = (int*)&sp;
        for (int i = threadIdx.x; i < n; i += NT) dst[i] = src[i];
    }
    __syncthreads();

    int gt = blockIdx.x * NT + threadIdx.x;
    int e = gt >> 2;
    int q = gt & 3;                 // quarter: positions 4q..4q+3
    if (e >= B) return;
    const int grp = threadIdx.x >> 2;
    const unsigned FULL = 0xffffffffu;
    const int selF = (q == 0) ? 1 : 0;
    const int selL = (q == 3) ? 1 : 0;

    // ---- conv0 + bn0 + sign -> v0[1..4] ----------------------------------
    unsigned v0[6];
#pragma unroll
    for (int k = 0; k < 6; k++) v0[k] = 0;
    {
        const float* xb = x + (size_t)e * 64 + q * 4;
        float4 c0v = *(const float4*)(xb + 0);
        float4 c1v = *(const float4*)(xb + 16);
        float4 c2v = *(const float4*)(xb + 32);
        float4 c3v = *(const float4*)(xb + 48);
        float a0[4] = {c0v.x, c0v.y, c0v.z, c0v.w};
        float a1[4] = {c1v.x, c1v.y, c1v.z, c1v.w};
        float a2[4] = {c2v.x, c2v.y, c2v.z, c2v.w};
        float a3[4] = {c3v.x, c3v.y, c3v.z, c3v.w};
        unsigned mask = 1u;
#pragma unroll 8
        for (int o = 0; o < 32; o++) {
            float4 pA = *(const float4*)&c_cp.c0[o][0];
            float4 pB = *(const float4*)&c_cp.c0[o][4];
#pragma unroll
            for (int j = 0; j < 4; j++) {
                float y = pA.x * a0[j];
                y = fmaf(pA.y, a1[j], y);
                y = fmaf(pA.z, a2[j], y);
                y = fmaf(pA.w, a3[j], y);
                float t1 = y + pB.x;
                float t2 = t1 - pB.y;
                float v = fmaf(t2, pB.z, pB.w);
                if (v >= 0.f) v0[j + 1] |= mask;
            }
            mask <<= 1;
        }
    }
    // halo for s0 plane (phantom zeros at outer edges)
    {
        unsigned up = __shfl_up_sync(FULL, v0[4], 1);
        unsigned dn = __shfl_down_sync(FULL, v0[1], 1);
        v0[0] = (q == 0) ? 0u : up;
        v0[5] = (q == 3) ? 0u : dn;
    }

    // ---- block 0: single plane -------------------------------------------
    unsigned vc[6], un[4];
    vc[0] = 0; vc[5] = 0;
#pragma unroll
    for (int j = 0; j < 4; j++) un[j] = 0;
    {
        const int* tip = c_cp.thrA[0][0];
        const int* tfp = c_cp.thrA[0][selF];
        const int* tlp = c_cp.thrB[0][selL];
        unsigned mask = 1u;
#pragma unroll 8
        for (int o = 0; o < 32; o++) {
            unsigned w0 = c_cp.Wb[0][o][0], w1 = c_cp.Wb[0][o][1], w2 = c_cp.Wb[0][o][2];
            int ti = tip[o], tf = tfp[o], tl = tlp[o];
#pragma unroll
            for (int j = 0; j < 4; j++) {
                int P = __popc(v0[j] ^ w0) + __popc(v0[j + 1] ^ w1) + __popc(v0[j + 2] ^ w2);
                int thr = (j == 0) ? tf : (j == 3) ? tl : ti;
                if (P <= thr) un[j] |= mask;
            }
            mask <<= 1;
        }
    }
#pragma unroll
    for (int j = 0; j < 4; j++) vc[j + 1] = un[j];

    // ---- blocks 1..3: two planes, masked-tap carry-save --------------------
#pragma unroll 1
    for (int i = 1; i < 4; i++) {
        {
            unsigned up = __shfl_up_sync(FULL, vc[4], 1);
            unsigned dn = __shfl_down_sync(FULL, vc[1], 1);
            vc[0] = (q == 0) ? 0u : up;
            vc[5] = (q == 3) ? 0u : dn;
        }
        unsigned mb[6];
        int DI[4];
        {
            int pm[6];
#pragma unroll
            for (int k = 0; k < 6; k++) {
                mb[k] = ~(v0[k] ^ vc[k]);     // xnor: phantom -> ~0 automatically
                pm[k] = __popc(mb[k]);
            }
#pragma unroll
            for (int j = 0; j < 4; j++) DI[j] = 96 - (pm[j] + pm[j + 1] + pm[j + 2]);
        }
#pragma unroll
        for (int j = 0; j < 4; j++) un[j] = 0;
        const int* tip = c_cp.thrA[i][0];
        const int* tfp = c_cp.thrA[i][selF];
        const int* tlp = c_cp.thrB[i][selL];
        unsigned mask = 1u;
#pragma unroll 8
        for (int o = 0; o < 32; o++) {
            unsigned w0 = c_cp.Wb[i][o][0], w1 = c_cp.Wb[i][o][1], w2 = c_cp.Wb[i][o][2];
            int ti = tip[o], tf = tfp[o], tl = tlp[o];
#pragma unroll
            for (int j = 0; j < 4; j++) {
                int Pc = __popc(xand(v0[j],     w0, mb[j]))
                       + __popc(xand(v0[j + 1], w1, mb[j + 1]))
                       + __popc(xand(v0[j + 2], w2, mb[j + 2]));
                int thr = (j == 0) ? tf : (j == 3) ? tl : ti;
                if (2 * Pc + DI[j] <= thr) un[j] |= mask;
            }
            mask <<= 1;
        }
#pragma unroll
        for (int j = 0; j < 4; j++) vc[j + 1] = un[j];
    }

    // ---- stash planes for full-width fc1 (vectorized) ----------------------
    {
        uint4* dst = (uint4*)&buf[grp][4 * q];
        dst[0] = make_uint4(v0[1], v0[2], v0[3], v0[4]);
        uint4* dst2 = (uint4*)&buf[grp][16 + 4 * q];
        dst2[0] = make_uint4(vc[1], vc[2], vc[3], vc[4]);
    }
    __syncwarp();

    unsigned f0[16], mbf[16];
    int Dsum;
    {
        int pms = 0;
        const uint4* b4 = (const uint4*)&buf[grp][0];
#pragma unroll
        for (int c = 0; c < 4; c++) {
            uint4 A = b4[c];
            uint4 Bv = b4[4 + c];
            f0[4 * c + 0] = A.x; f0[4 * c + 1] = A.y;
            f0[4 * c + 2] = A.z; f0[4 * c + 3] = A.w;
            mbf[4 * c + 0] = ~(A.x ^ Bv.x);
            mbf[4 * c + 1] = ~(A.y ^ Bv.y);
            mbf[4 * c + 2] = ~(A.z ^ Bv.z);
            mbf[4 * c + 3] = ~(A.w ^ Bv.w);
            pms += __popc(mbf[4 * c + 0]) + __popc(mbf[4 * c + 1])
                 + __popc(mbf[4 * c + 2]) + __popc(mbf[4 * c + 3]);
        }
        Dsum = 512 - pms;
    }

    // ---- fc1: outputs o = q + 4*oo (vectorized weight loads) ---------------
    unsigned hb = 0;
#pragma unroll 2
    for (int oo = 0; oo < 16; oo++) {
        int o = q + 4 * oo;
        const uint4* wv = (const uint4*)&sp.W1p[o][0];
        int Pc = 0;
#pragma unroll
        for (int c = 0; c < 4; c++) {
            uint4 W = wv[c];
            Pc += __popc(xand(f0[4 * c + 0], W.x, mbf[4 * c + 0]))
                + __popc(xand(f0[4 * c + 1], W.y, mbf[4 * c + 1]))
                + __popc(xand(f0[4 * c + 2], W.z, mbf[4 * c + 2]))
                + __popc(xand(f0[4 * c + 3], W.w, mbf[4 * c + 3]));
        }
        if (2 * Pc + Dsum <= sp.P5[o]) hb |= 1u << oo;
    }
    // assemble permuted h words
    unsigned t1 = __shfl_xor_sync(FULL, hb, 1);
    unsigned pw = (q & 1) ? ((hb << 16) | t1) : ((t1 << 16) | hb);
    unsigned t2 = __shfl_xor_sync(FULL, pw, 2);
    unsigned hw0 = (q < 2) ? pw : t2;
    unsigned hw1 = (q < 2) ? t2 : pw;

    // ---- fc2: outputs o = q + 4*oo ------------------------------------------
    unsigned gb = 0;
#pragma unroll 4
    for (int oo = 0; oo < 16; oo++) {
        int o = q + 4 * oo;
        uint2 W = *(const uint2*)&sp.W2p[o][0];
        int P = __popc(hw0 ^ W.x) + __popc(hw1 ^ W.y);
        if (P <= sp.P6[o]) gb |= 1u << oo;
    }
    t1 = __shfl_xor_sync(FULL, gb, 1);
    pw = (q & 1) ? ((gb << 16) | t1) : ((t1 << 16) | gb);
    t2 = __shfl_xor_sync(FULL, pw, 2);
    unsigned gw0 = (q < 2) ? pw : t2;
    unsigned gw1 = (q < 2) ? t2 : pw;

    // ---- fc3 + sigmoid LUT ----------------------------------------------------
    if (q == 0) {
        int p3 = __popc(gw0 ^ sp.W3p[0]) + __popc(gw1 ^ sp.W3p[1]);
        out[e] = sp.sig[p3];
    }
}

extern "C" void kernel_launch(void* const* d_in, const int* in_sizes, int n_in,
                              void* d_out, int out_size)
{
    const float* x       = (const float*)d_in[0];
    const float* conv0_w = (const float*)d_in[1];
    const float* conv0_b = (const float*)d_in[2];
    const float* bn0_g   = (const float*)d_in[3];
    const float* bn0_b   = (const float*)d_in[4];
    const float* bn0_m   = (const float*)d_in[5];
    const float* bn0_v   = (const float*)d_in[6];
    const float* convs_w = (const float*)d_in[7];
    const float* convs_b = (const float*)d_in[8];
    const float* bns_g   = (const float*)d_in[9];
    const float* bns_b   = (const float*)d_in[10];
    const float* bns_m   = (const float*)d_in[11];
    const float* bns_v   = (const float*)d_in[12];
    const float* fc1_w   = (const float*)d_in[13];
    const float* fc1_b   = (const float*)d_in[14];
    const float* bn5_g   = (const float*)d_in[15];
    const float* bn5_b   = (const float*)d_in[16];
    const float* bn5_m   = (const float*)d_in[17];
    const float* bn5_v   = (const float*)d_in[18];
    const float* fc2_w   = (const float*)d_in[19];
    const float* fc2_b   = (const float*)d_in[20];
    const float* bn6_g   = (const float*)d_in[21];
    const float* bn6_b   = (const float*)d_in[22];
    const float* bn6_m   = (const float*)d_in[23];
    const float* bn6_v   = (const float*)d_in[24];
    const float* fc3_w   = (const float*)d_in[25];
    const float* fc3_b   = (const float*)d_in[26];

    int B = in_sizes[0] / 64;   // (B, 4, 16)
    float* out = (float*)d_out;

    prep_kernel<<<1, 256>>>(conv0_w, conv0_b, bn0_g, bn0_b, bn0_m, bn0_v,
                            convs_w, convs_b, bns_g, bns_b, bns_m, bns_v,
                            fc1_w, fc1_b, bn5_g, bn5_b, bn5_m, bn5_v,
                            fc2_w, fc2_b, bn6_g, bn6_b, bn6_m, bn6_v,
                            fc3_w, fc3_b);

    void* srcp = nullptr;
    cudaGetSymbolAddress(&srcp, g_cp);
    cudaMemcpyToSymbolAsync(c_cp, srcp, sizeof(CP), 0, cudaMemcpyDeviceToDevice, 0);

    long long totalThreads = 4LL * B;
    int blocks = (int)((totalThreads + NT - 1) / NT);
    bnn_kernel<<<blocks, NT>>>(x, out, B);
}